// round 4
// baseline (speedup 1.0000x reference)
#include <cuda_runtime.h>

// Problem constants (fixed by the reference)
#define SEQ   1024
#define BSZ   16
#define DIM   1024
#define SIDE  32
#define BD    (BSZ * DIM)      // floats between consecutive seq positions

#define DPB   4                // d-channels per block = warps per block
#define IPB   8                // images (batch entries) per block / per warp
#define CPL   8                // columns per lane
#define RCH   8                // rows staged per chunk
#define NCH   (SIDE / RCH)     // 4 chunks
#define IMS   33               // image stride in floats (conflict-free)
#define CHS   264              // channel stride = 8*33 (== 8 mod 32)

// out[s,b,d] = silu( conv2d_causal(x, K_d)[s] + x[s,b,d]*omega[d] )
// computed by running the 2-state 2D SSM recurrence directly on x.
// Warp = one channel d, 8 images; lane (g = lane>>3, i = lane&7) owns
// columns 8g..8g+7 of image i. Horizontal recurrence: 7 serial FMAs in-lane
// + 2-step coefficient scan over the 4-lane group {i, i+8, i+16, i+24}.
__global__ __launch_bounds__(128, 5) void ssm2d_kernel(
    const float* __restrict__ x,
    const float* __restrict__ A1, const float* __restrict__ A2,
    const float* __restrict__ B1, const float* __restrict__ B2,
    const float* __restrict__ C1, const float* __restrict__ C2,
    const float* __restrict__ omega,
    float* __restrict__ out)
{
    __shared__ float buf[RCH][DPB * CHS];

    const int tid  = threadIdx.x;
    const int w    = tid >> 5;          // warp id == channel within block
    const int lane = tid & 31;
    const int ii   = lane & 7;          // image index within warp (0..7)
    const int g    = lane >> 3;         // column-group (0..3), cols 8g..8g+7

    const int d0 = blockIdx.x * DPB;
    const int b0 = blockIdx.y * IPB;
    const int d  = d0 + w;

    // loader role: tid -> ch fastest (16B contiguous gmem), then image, then col-quarter
    const int lch  = tid & 3;
    const int limg = (tid >> 2) & 7;
    const int lcq  = tid >> 5;          // 0..3 (covers cols lcq*8 .. lcq*8+7)
    const int gbase = (b0 + limg) * DIM + d0 + lch;
    const int sbase = lch * CHS + limg * IMS;

    const float SC = 0.70710678118654752440f;  // sqrt(1/2)

    // per-channel parameters (broadcast within warp)
    float a1[2], a2[2], b1[2], b2[2], c1[2], c2[2];
#pragma unroll
    for (int k = 0; k < 2; ++k) {
        a1[k] = 0.5f / (1.f + __expf(-A1[d * 2 + k]));
        a2[k] = 0.5f / (1.f + __expf(-A2[d * 2 + k]));
        b1[k] = 0.5f / (1.f + __expf(-B1[d * 2 + k]));
        b2[k] = 0.5f / (1.f + __expf(-B2[d * 2 + k]));
        c1[k] = C1[d * 2 + k] * SC;
        c2[k] = C2[d * 2 + k] * SC;
    }
    const float om = omega[d];

    // powers of a1: p[k][j] = a1^(j+1), j = 0..7 ; plus a1^16 for scan step 2
    float p[2][8], p16[2];
#pragma unroll
    for (int k = 0; k < 2; ++k) {
        p[k][0] = a1[k];
#pragma unroll
        for (int j = 1; j < 8; ++j) p[k][j] = p[k][j - 1] * a1[k];
        p16[k] = p[k][7] * p[k][7];
    }

    // previous-row state for this lane's 8 columns, both components
    float h[2][CPL], v[2][CPL];
#pragma unroll
    for (int k = 0; k < 2; ++k)
#pragma unroll
        for (int cc = 0; cc < CPL; ++cc) { h[k][cc] = 0.f; v[k][cc] = 0.f; }

    const int rdbase = w * CHS + ii * IMS + g * CPL;

    for (int c = 0; c < NCH; ++c) {
        // ---- stage RCH rows x 8 images x 4 channels ----
#pragma unroll
        for (int r = 0; r < RCH; ++r) {
            const int srow = (c * RCH + r) * SIDE;
#pragma unroll
            for (int cc = 0; cc < 8; ++cc) {
                const int col = lcq * 8 + cc;
                buf[r][sbase + col] = x[(srow + col) * BD + gbase];
            }
        }
        __syncthreads();

        // ---- recurrence ----
#pragma unroll
        for (int r = 0; r < RCH; ++r) {
            float xs[CPL];
#pragma unroll
            for (int cc = 0; cc < CPL; ++cc) xs[cc] = buf[r][rdbase + cc];

            float o[CPL];
#pragma unroll
            for (int cc = 0; cc < CPL; ++cc) o[cc] = om * xs[cc];

#pragma unroll
            for (int k = 0; k < 2; ++k) {
                // vertical update (elementwise per column), in place
#pragma unroll
                for (int cc = 0; cc < CPL; ++cc)
                    v[k][cc] = fmaf(a2[k], h[k][cc],
                               fmaf(a1[k], v[k][cc], b2[k] * xs[cc]));

                // v of the column left of this lane's chunk (prev group's col 7)
                float vl = __shfl_up_sync(0xffffffffu, v[k][7], 8);
                if (g == 0) vl = 0.f;

                // local serial prefix: Y_c = a1*Y_{c-1} + a2*v_{c-1} + b1*x_c
                float Y[CPL];
                Y[0] = fmaf(a2[k], vl, b1[k] * xs[0]);
#pragma unroll
                for (int cc = 1; cc < CPL; ++cc)
                    Y[cc] = fmaf(a1[k], Y[cc - 1],
                            fmaf(a2[k], v[k][cc - 1], b1[k] * xs[cc]));

                // 2-step scan over the 4-lane group, coefficient a1^8
                float S = Y[7], t;
                t = __shfl_up_sync(0xffffffffu, S, 8);
                if (g >= 1) S = fmaf(p[k][7], t, S);
                t = __shfl_up_sync(0xffffffffu, S, 16);
                if (g >= 2) S = fmaf(p16[k], t, S);

                // incoming h at the left chunk boundary
                float hin = __shfl_up_sync(0xffffffffu, S, 8);
                if (g == 0) hin = 0.f;

                // reconstruct h for the 8 owned columns and project
#pragma unroll
                for (int cc = 0; cc < CPL; ++cc) {
                    h[k][cc] = fmaf(p[k][cc], hin, Y[cc]);
                    o[cc] = fmaf(c1[k], h[k][cc], fmaf(c2[k], v[k][cc], o[cc]));
                }
            }

            // silu + stage output (same slots this thread read -> no hazard)
#pragma unroll
            for (int cc = 0; cc < CPL; ++cc) {
                const float y = o[cc];
                buf[r][rdbase + cc] = y * __fdividef(1.f, 1.f + __expf(-y));
            }
        }
        __syncthreads();

        // ---- write back ----
#pragma unroll
        for (int r = 0; r < RCH; ++r) {
            const int srow = (c * RCH + r) * SIDE;
#pragma unroll
            for (int cc = 0; cc < 8; ++cc) {
                const int col = lcq * 8 + cc;
                out[(srow + col) * BD + gbase] = buf[r][sbase + col];
            }
        }
        __syncthreads();
    }
}

extern "C" void kernel_launch(void* const* d_in, const int* in_sizes, int n_in,
                              void* d_out, int out_size)
{
    const float* x     = (const float*)d_in[0];
    const float* A1    = (const float*)d_in[1];
    const float* A2    = (const float*)d_in[2];
    const float* B1    = (const float*)d_in[3];
    const float* B2    = (const float*)d_in[4];
    const float* C1    = (const float*)d_in[5];
    const float* C2    = (const float*)d_in[6];
    const float* omega = (const float*)d_in[7];
    float* out = (float*)d_out;

    dim3 block(DPB * 32);                 // 128 threads
    dim3 grid(DIM / DPB, BSZ / IPB);      // 256 x 2 = 512 blocks
    ssm2d_kernel<<<grid, block>>>(x, A1, A2, B1, B2, C1, C2, omega, out);
}

// round 6
// speedup vs baseline: 1.5191x; 1.5191x over previous
#include <cuda_runtime.h>

// Problem constants (fixed by the reference)
#define SEQ   1024
#define BSZ   16
#define DIM   1024
#define SIDE  32
#define BD    (BSZ * DIM)      // floats between consecutive seq positions

#define DPB   8                // d-channels per block = warps per block
#define IPB   4                // images (batch entries) per block / per warp
#define RCH   4                // rows staged per chunk
#define NCH   (SIDE / RCH)     // 8 chunks
#define LDD   132              // 4 images * 32 cols + 4 pad floats

// out[s,b,d] = silu( conv2d_causal(x, K_d)[s] + x[s,b,d]*omega[d] )
// via running the 2-state 2D SSM recurrence directly on x.
// Warp = one channel d, 4 images; lane (ib=lane>>3, g=lane&7) owns cols 4g..4g+3.
// Chunks of 4 rows are software-pipelined: next chunk's gmem loads are issued
// into registers before computing the current chunk (double-buffered smem).
__global__ __launch_bounds__(256, 3) void ssm2d_kernel(
    const float* __restrict__ x,
    const float* __restrict__ A1, const float* __restrict__ A2,
    const float* __restrict__ B1, const float* __restrict__ B2,
    const float* __restrict__ C1, const float* __restrict__ C2,
    const float* __restrict__ omega,
    float* __restrict__ out)
{
    __shared__ __align__(16) float buf[2][RCH][DPB][LDD];

    const int tid  = threadIdx.x;
    const int w    = tid >> 5;          // warp id == channel within block
    const int lane = tid & 31;
    const int ib   = lane >> 3;         // image index within warp (0..3)
    const int g    = lane & 7;          // column-group (cols 4g..4g+3)

    const int d0 = blockIdx.x * DPB;
    const int b0 = blockIdx.y * IPB;
    const int d  = d0 + w;

    // loader/writeback role: float2 over channels (32B-sector exact)
    const int lch2 = tid & 3;           // channel pair -> ch = 2*lch2
    const int lcol = (tid >> 2) & 31;   // column
    const int lsub = tid >> 7;          // image half: images 2*lsub, 2*lsub+1
    const int ch   = 2 * lch2;

    const float SC = 0.70710678118654752440f;  // sqrt(1/2)

    // per-channel parameters (broadcast within warp)
    float a1[2], a2[2], b1[2], b2[2], c1[2], c2[2];
#pragma unroll
    for (int k = 0; k < 2; ++k) {
        a1[k] = 0.5f / (1.f + __expf(-A1[d * 2 + k]));
        a2[k] = 0.5f / (1.f + __expf(-A2[d * 2 + k]));
        b1[k] = 0.5f / (1.f + __expf(-B1[d * 2 + k]));
        b2[k] = 0.5f / (1.f + __expf(-B2[d * 2 + k]));
        c1[k] = C1[d * 2 + k] * SC;
        c2[k] = C2[d * 2 + k] * SC;
    }
    const float om = omega[d];

    // precomputed coefficient powers for scan & reconstruction
    float p2[2], p3[2], p4[2], p8[2], p16[2];
#pragma unroll
    for (int k = 0; k < 2; ++k) {
        p2[k]  = a1[k] * a1[k];
        p3[k]  = p2[k] * a1[k];
        p4[k]  = p2[k] * p2[k];
        p8[k]  = p4[k] * p4[k];
        p16[k] = p8[k] * p8[k];
    }

    // previous-row state for this lane's 4 columns, both components
    float h[2][4] = {{0.f,0.f,0.f,0.f},{0.f,0.f,0.f,0.f}};
    float v[2][4] = {{0.f,0.f,0.f,0.f},{0.f,0.f,0.f,0.f}};

    // ---- prologue: load + stage chunk 0 ----
    float2 R[RCH][2];
#pragma unroll
    for (int r = 0; r < RCH; ++r)
#pragma unroll
        for (int it = 0; it < 2; ++it) {
            const int i = 2 * lsub + it;
            const int s = r * SIDE + lcol;
            R[r][it] = *(const float2*)&x[s * BD + (b0 + i) * DIM + d0 + ch];
        }
#pragma unroll
    for (int r = 0; r < RCH; ++r)
#pragma unroll
        for (int it = 0; it < 2; ++it) {
            const int i = 2 * lsub + it;
            buf[0][r][ch    ][i * SIDE + lcol] = R[r][it].x;
            buf[0][r][ch + 1][i * SIDE + lcol] = R[r][it].y;
        }

    for (int c = 0; c < NCH; ++c) {
        const int p = c & 1;
        __syncthreads();   // staged chunk c visible; prior writeback reads done

        // issue next chunk's loads early (latency hidden under compute)
        if (c + 1 < NCH) {
#pragma unroll
            for (int r = 0; r < RCH; ++r)
#pragma unroll
                for (int it = 0; it < 2; ++it) {
                    const int i = 2 * lsub + it;
                    const int s = ((c + 1) * RCH + r) * SIDE + lcol;
                    R[r][it] = *(const float2*)&x[s * BD + (b0 + i) * DIM + d0 + ch];
                }
        }

        // ---- recurrence on chunk c ----
#pragma unroll
        for (int r = 0; r < RCH; ++r) {
            const float4 xv = *(const float4*)&buf[p][r][w][ib * SIDE + 4 * g];
            const float xs[4] = {xv.x, xv.y, xv.z, xv.w};

            float o0 = om * xs[0], o1 = om * xs[1];
            float o2 = om * xs[2], o3 = om * xs[3];

#pragma unroll
            for (int k = 0; k < 2; ++k) {
                // vertical update (elementwise per column)
                float v0 = fmaf(a2[k], h[k][0], fmaf(a1[k], v[k][0], b2[k] * xs[0]));
                float v1 = fmaf(a2[k], h[k][1], fmaf(a1[k], v[k][1], b2[k] * xs[1]));
                float v2 = fmaf(a2[k], h[k][2], fmaf(a1[k], v[k][2], b2[k] * xs[2]));
                float v3 = fmaf(a2[k], h[k][3], fmaf(a1[k], v[k][3], b2[k] * xs[3]));

                // v of the column left of this lane's chunk
                float vl = __shfl_up_sync(0xffffffffu, v3, 1);
                if (g == 0) vl = 0.f;

                // local serial prefix of h-drive
                float Y0 = fmaf(a2[k], vl, b1[k] * xs[0]);
                float Y1 = fmaf(a1[k], Y0, fmaf(a2[k], v0, b1[k] * xs[1]));
                float Y2 = fmaf(a1[k], Y1, fmaf(a2[k], v1, b1[k] * xs[2]));
                float Y3 = fmaf(a1[k], Y2, fmaf(a2[k], v2, b1[k] * xs[3]));

                // 3-step scan over 8-lane group, coefficient a1^4
                float S = Y3, t;
                t = __shfl_up_sync(0xffffffffu, S, 1);
                if (g >= 1) S = fmaf(p4[k], t, S);
                t = __shfl_up_sync(0xffffffffu, S, 2);
                if (g >= 2) S = fmaf(p8[k], t, S);
                t = __shfl_up_sync(0xffffffffu, S, 4);
                if (g >= 4) S = fmaf(p16[k], t, S);

                // incoming h at the left chunk boundary
                float hin = __shfl_up_sync(0xffffffffu, S, 1);
                if (g == 0) hin = 0.f;

                // reconstruct h for the 4 owned columns
                float h0 = fmaf(a1[k], hin, Y0);
                float h1 = fmaf(p2[k], hin, Y1);
                float h2 = fmaf(p3[k], hin, Y2);
                float h3 = fmaf(p4[k], hin, Y3);

                h[k][0] = h0; h[k][1] = h1; h[k][2] = h2; h[k][3] = h3;
                v[k][0] = v0; v[k][1] = v1; v[k][2] = v2; v[k][3] = v3;

                o0 = fmaf(c1[k], h0, fmaf(c2[k], v0, o0));
                o1 = fmaf(c1[k], h1, fmaf(c2[k], v1, o1));
                o2 = fmaf(c1[k], h2, fmaf(c2[k], v2, o2));
                o3 = fmaf(c1[k], h3, fmaf(c2[k], v3, o3));
            }

            // silu + stage output in place (same slot this thread read)
            float4 ov;
            ov.x = o0 * __fdividef(1.f, 1.f + __expf(-o0));
            ov.y = o1 * __fdividef(1.f, 1.f + __expf(-o1));
            ov.z = o2 * __fdividef(1.f, 1.f + __expf(-o2));
            ov.w = o3 * __fdividef(1.f, 1.f + __expf(-o3));
            *(float4*)&buf[p][r][w][ib * SIDE + 4 * g] = ov;
        }

        __syncthreads();   // silu results visible

        // stage next chunk into the other buffer (data arrived during compute)
        if (c + 1 < NCH) {
#pragma unroll
            for (int r = 0; r < RCH; ++r)
#pragma unroll
                for (int it = 0; it < 2; ++it) {
                    const int i = 2 * lsub + it;
                    buf[p ^ 1][r][ch    ][i * SIDE + lcol] = R[r][it].x;
                    buf[p ^ 1][r][ch + 1][i * SIDE + lcol] = R[r][it].y;
                }
        }

        // ---- write back chunk c (float2 over channels, 32B sectors) ----
#pragma unroll
        for (int r = 0; r < RCH; ++r)
#pragma unroll
            for (int it = 0; it < 2; ++it) {
                const int i = 2 * lsub + it;
                const int s = (c * RCH + r) * SIDE + lcol;
                float2 o2v;
                o2v.x = buf[p][r][ch    ][i * SIDE + lcol];
                o2v.y = buf[p][r][ch + 1][i * SIDE + lcol];
                *(float2*)&out[s * BD + (b0 + i) * DIM + d0 + ch] = o2v;
            }
    }
}

extern "C" void kernel_launch(void* const* d_in, const int* in_sizes, int n_in,
                              void* d_out, int out_size)
{
    const float* x     = (const float*)d_in[0];
    const float* A1    = (const float*)d_in[1];
    const float* A2    = (const float*)d_in[2];
    const float* B1    = (const float*)d_in[3];
    const float* B2    = (const float*)d_in[4];
    const float* C1    = (const float*)d_in[5];
    const float* C2    = (const float*)d_in[6];
    const float* omega = (const float*)d_in[7];
    float* out = (float*)d_out;

    dim3 block(DPB * 32);                 // 256 threads
    dim3 grid(DIM / DPB, BSZ / IPB);      // 128 x 4 = 512 blocks
    ssm2d_kernel<<<grid, block>>>(x, A1, A2, B1, B2, C1, C2, omega, out);
}